// round 8
// baseline (speedup 1.0000x reference)
#include <cuda_runtime.h>
#include <math.h>

#define BB 4
#define SS 4096
#define DD 1024
#define ND 4096                 // floats per (b,s) row
#define ND4 1024                // float4 per row
#define D4 256                  // float4 per stream row
#define NCOLS 24
#define GA 16                   // gate col-blocks per batch (64 total)
#define MAXBLK 512

// Scratch (allocation-free rule: __device__ globals)
__device__ float4 g_colpart[MAXBLK][ND4];        // per-block column partials (8 MB)
__device__ float  g_dpart[BB][GA][NCOLS];        // gate dot partials
__device__ float  g_ssp[BB][GA];                 // sum-of-squares partials
__device__ float  g_gates[BB][24];               // pre[4], post[4], P[16]
__device__ unsigned g_gen[4];                    // barrier generations (monotonic)
__device__ unsigned g_cnt[4];                    // barrier counts (self-reset)

// Reusable grid barrier: generation monotonic across graph replays, count
// self-resets -> deterministic + replay-safe.
__device__ __forceinline__ void gbar(int i) {
    __syncthreads();
    if (threadIdx.x == 0) {
        __threadfence();
        const unsigned gen = atomicAdd(&g_gen[i], 0u);
        const unsigned t = atomicAdd(&g_cnt[i], 1u);
        if (t == gridDim.x - 1) {
            g_cnt[i] = 0;
            __threadfence();
            atomicExch(&g_gen[i], gen + 1u);
        } else {
            while (atomicAdd(&g_gen[i], 0u) == gen) { }
        }
        __threadfence();
    }
    __syncthreads();
}

__global__ void __launch_bounds__(512, 2)
k_fused(const float* __restrict__ H,
        const float* __restrict__ bo,
        const float* __restrict__ phi,
        const float* __restrict__ pre_base,
        const float* __restrict__ post_base,
        const float* __restrict__ res_base,
        const float* __restrict__ a_pre,
        const float* __restrict__ a_post,
        const float* __restrict__ a_res,
        float* __restrict__ out) {
    const int t   = threadIdx.x;             // 0..511
    const int blk = blockIdx.x;
    const int nb  = gridDim.x >> 2;          // blocks per batch
    const int b   = blk / nb;
    const int ib  = blk % nb;
    const int r0  = (ib * SS) / nb;          // own row span [r0, r1)
    const int r1  = ((ib + 1) * SS) / nb;

    // ============ Phase 1: column partial sums over own rows (ascending) ====
    // Evict-normal loads: the TAIL of this block's span is L2-resident when
    // phase 3 re-reads it DESCENDING (per-block LIFO reuse).
    {
        const float4* Hb = (const float4*)H + (size_t)b * SS * ND4;
        float4 acc0 = make_float4(0.f, 0.f, 0.f, 0.f);
        float4 acc1 = make_float4(0.f, 0.f, 0.f, 0.f);
#pragma unroll 4
        for (int r = r0; r < r1; r++) {
            const float4* p = Hb + (size_t)r * ND4;
            const float4 v0 = p[t];
            const float4 v1 = p[t + 512];
            acc0.x += v0.x; acc0.y += v0.y; acc0.z += v0.z; acc0.w += v0.w;
            acc1.x += v1.x; acc1.y += v1.y; acc1.z += v1.z; acc1.w += v1.w;
        }
        g_colpart[blk][t]       = acc0;
        g_colpart[blk][t + 512] = acc1;
    }

    gbar(0);

    // ============ Phase 2a: gate reductions (first 64 blocks) ===============
    // Block-scope smem + unconditional __syncthreads between warp-partial
    // writes and the cross-warp combine (fixes R7 race).
    __shared__ float sred[8][NCOLS];
    __shared__ float sss[8];

    const bool gate_blk = (blk < BB * GA);
    if (gate_blk && t < 256) {
        const int b2   = blk >> 4;
        const int g    = blk & 15;
        const int col  = g * 256 + t;
        const int lane = t & 31;
        const int warp = t >> 5;              // 0..7

        float x = 0.0f;
        for (int j = 0; j < nb; j++)
            x += ((const float*)g_colpart[b2 * nb + j])[col];
        x *= (1.0f / (float)SS);

        float acc24[NCOLS];
        const float* ph = phi + (size_t)col * NCOLS;
#pragma unroll
        for (int j = 0; j < NCOLS; j++) acc24[j] = x * ph[j];
        float ss = x * x;

#pragma unroll
        for (int o = 16; o > 0; o >>= 1) {
            ss += __shfl_down_sync(0xffffffffu, ss, o);
#pragma unroll
            for (int j = 0; j < NCOLS; j++)
                acc24[j] += __shfl_down_sync(0xffffffffu, acc24[j], o);
        }
        if (lane == 0) {
#pragma unroll
            for (int j = 0; j < NCOLS; j++) sred[warp][j] = acc24[j];
            sss[warp] = ss;
        }
    }
    __syncthreads();                          // ALL threads: cross-warp visibility
    if (gate_blk) {
        const int b2 = blk >> 4;
        const int g  = blk & 15;
        if (t < NCOLS) {
            float v = 0.0f;
#pragma unroll
            for (int w = 0; w < 8; w++) v += sred[w][t];
            g_dpart[b2][g][t] = v;
        } else if (t == NCOLS) {
            float v = 0.0f;
#pragma unroll
            for (int w = 0; w < 8; w++) v += sss[w];
            g_ssp[b2][g] = v;
        }
    }

    gbar(1);

    // ============ Phase 2b: combine + sigmoids + Sinkhorn (block 0) =========
    if (blk == 0 && t < 128) {
        const int bb   = t >> 5;              // warp = batch
        const int lane = t & 31;

        __shared__ float sdelta[BB][NCOLS];

        float invrms = 0.0f;
        if (lane == 0) {
            float ssum = 0.0f;
#pragma unroll
            for (int k = 0; k < GA; k++) ssum += g_ssp[bb][k];
            invrms = 1.0f / sqrtf(ssum * (1.0f / (float)ND) + 1e-6f);
        }
        invrms = __shfl_sync(0xffffffffu, invrms, 0);

        if (lane < NCOLS) {
            float v = 0.0f;
#pragma unroll
            for (int k = 0; k < GA; k++) v += g_dpart[bb][k][lane];
            sdelta[bb][lane] = v * invrms;
        }
        __syncwarp();

        if (lane == 0) {
            const float ap  = *a_pre;
            const float apo = *a_post;
            const float ar  = *a_res;

            float pre[4];
            float psum = 0.0f;
#pragma unroll
            for (int k = 0; k < 4; k++) {
                pre[k] = 1.0f / (1.0f + expf(-(pre_base[k] + ap * sdelta[bb][k])));
                psum += pre[k];
            }
            const float pinv = 1.0f / (psum + 1e-8f);
#pragma unroll
            for (int k = 0; k < 4; k++) g_gates[bb][k] = pre[k] * pinv;

#pragma unroll
            for (int k = 0; k < 4; k++)
                g_gates[bb][4 + k] =
                    1.0f / (1.0f + expf(-(post_base[k] + apo * sdelta[bb][4 + k])));

            float P[16];
#pragma unroll
            for (int q = 0; q < 16; q++)
                P[q] = expf(res_base[q] + ar * sdelta[bb][8 + q]);
            for (int it = 0; it < 20; it++) {
#pragma unroll
                for (int i = 0; i < 4; i++) {
                    const float rs = P[i*4+0] + P[i*4+1] + P[i*4+2] + P[i*4+3];
                    const float inv = 1.0f / (rs + 1e-6f);
                    P[i*4+0] *= inv; P[i*4+1] *= inv; P[i*4+2] *= inv; P[i*4+3] *= inv;
                }
#pragma unroll
                for (int j = 0; j < 4; j++) {
                    const float cs = P[0*4+j] + P[1*4+j] + P[2*4+j] + P[3*4+j];
                    const float inv = 1.0f / (cs + 1e-6f);
                    P[0*4+j] *= inv; P[1*4+j] *= inv; P[2*4+j] *= inv; P[3*4+j] *= inv;
                }
            }
#pragma unroll
            for (int q = 0; q < 16; q++) g_gates[bb][8 + q] = P[q];
        }
    }

    gbar(2);

    // ============ Phase 3: mix own rows DESCENDING (LIFO L2 reuse) ==========
    __shared__ float sg[24];
    if (t < 24) sg[t] = g_gates[b][t];
    __syncthreads();

    const int half = t >> 8;                  // 0/1: which row of the pair
    const int d4   = t & 255;

    for (int base = r1 - 2; base >= r0 - 1; base -= 2) {
        const int row = base + 1 - half;
        if (row < r0) continue;               // odd-length span, last iter
        const int bs = b * SS + row;

        const float4* hb = (const float4*)H + (size_t)bs * ND4;
        const float4 h0 = hb[0 * D4 + d4];    // default policy: want L2 hits
        const float4 h1 = hb[1 * D4 + d4];
        const float4 h2 = hb[2 * D4 + d4];
        const float4 h3 = hb[3 * D4 + d4];
        const float4 bv = __ldcs((const float4*)bo + (size_t)bs * D4 + d4);

        float4* ob = (float4*)out + (size_t)bs * 5 * D4;

        float4 o;
        o.x = sg[0]*h0.x + sg[1]*h1.x + sg[2]*h2.x + sg[3]*h3.x;
        o.y = sg[0]*h0.y + sg[1]*h1.y + sg[2]*h2.y + sg[3]*h3.y;
        o.z = sg[0]*h0.z + sg[1]*h1.z + sg[2]*h2.z + sg[3]*h3.z;
        o.w = sg[0]*h0.w + sg[1]*h1.w + sg[2]*h2.w + sg[3]*h3.w;
        __stcs(ob + d4, o);

#pragma unroll
        for (int i = 0; i < 4; i++) {
            const float p0 = sg[8 + i * 4 + 0];
            const float p1 = sg[8 + i * 4 + 1];
            const float p2 = sg[8 + i * 4 + 2];
            const float p3 = sg[8 + i * 4 + 3];
            const float pp = sg[4 + i];
            float4 u;
            u.x = p0*h0.x + p1*h1.x + p2*h2.x + p3*h3.x + pp*bv.x;
            u.y = p0*h0.y + p1*h1.y + p2*h2.y + p3*h3.y + pp*bv.y;
            u.z = p0*h0.z + p1*h1.z + p2*h2.z + p3*h3.z + pp*bv.z;
            u.w = p0*h0.w + p1*h1.w + p2*h2.w + p3*h3.w + pp*bv.w;
            __stcs(ob + (1 + i) * D4 + d4, u);
        }
    }
}

// ---------------------------------------------------------------------------
extern "C" void kernel_launch(void* const* d_in, const int* in_sizes, int n_in,
                              void* d_out, int out_size) {
    const float* H         = (const float*)d_in[0];
    const float* branch_o  = (const float*)d_in[1];
    const float* phi       = (const float*)d_in[2];
    const float* pre_base  = (const float*)d_in[3];
    const float* post_base = (const float*)d_in[4];
    const float* res_base  = (const float*)d_in[5];
    const float* a_pre     = (const float*)d_in[6];
    const float* a_post    = (const float*)d_in[7];
    const float* a_res     = (const float*)d_in[8];
    float* out = (float*)d_out;

    int nsm = 0;
    cudaDeviceGetAttribute(&nsm, cudaDevAttrMultiProcessorCount, 0);
    int grid = 2 * nsm;            // 2 co-resident blocks/SM (512 thr each)
    if (grid > MAXBLK) grid = MAXBLK;
    grid &= ~3;                    // divisible by 4 (batches)

    k_fused<<<grid, 512>>>(H, branch_o, phi, pre_base, post_base, res_base,
                           a_pre, a_post, a_res, out);
}

// round 10
// speedup vs baseline: 1.0269x; 1.0269x over previous
#include <cuda_runtime.h>
#include <math.h>

#define BB 4
#define SS 4096
#define DD 1024
#define ND 4096                   // floats per (b,s)
#define ND4 1024                  // float4 per (b,s)
#define D4 256                    // float4 per stream row
#define NCOLS 24
#define SCHUNKS 32
#define SPERCHUNK 128
#define GA 16                     // gate col-blocks per batch (64 total)

// Scratch (allocation-free rule: __device__ globals)
__device__ float    g_partial[BB][SCHUNKS][ND];    // 2 MB
__device__ float    g_dpart[BB][GA][NCOLS];
__device__ float    g_ssp[BB][GA];
__device__ float    g_gates[BB][24];               // pre[4], post[4], P[16]
__device__ unsigned g_gcnt;                        // gate-block completion counter

// ---------------------------------------------------------------------------
// Kernel 1: column partial sums over S, per 128-row chunk, s DESCENDING so the
// head half of every chunk is L2-resident at kernel end (consumed first by the
// hot half of k_mix). Evict-normal loads. grid (4, 32, 4) x 256.
// ---------------------------------------------------------------------------
__global__ void __launch_bounds__(256) k_reduce(const float4* __restrict__ H4) {
    const int b     = blockIdx.z;
    const int chunk = blockIdx.y;
    const int col4  = blockIdx.x * 256 + threadIdx.x;
    const float4* base = H4 + ((size_t)b * SS + (size_t)chunk * SPERCHUNK) * ND4 + col4;
    float4 acc = make_float4(0.f, 0.f, 0.f, 0.f);
#pragma unroll 16
    for (int s = SPERCHUNK - 1; s >= 0; s--) {
        const float4 v = base[(size_t)s * ND4];
        acc.x += v.x; acc.y += v.y; acc.z += v.z; acc.w += v.w;
    }
    ((float4*)&g_partial[b][chunk][0])[col4] = acc;
}

// ---------------------------------------------------------------------------
// Kernel 2: fused gate reduction + finalize. 64 blocks x 256 threads.
// Each block reduces 256 columns of one batch -> 24 dot partials + ss partial.
// The LAST block to finish (result is order-independent) combines partials
// and runs sigmoid/normalize/Sinkhorn.
// ---------------------------------------------------------------------------
__global__ void __launch_bounds__(256) k_gates(const float* __restrict__ phi,
                                               const float* __restrict__ pre_base,
                                               const float* __restrict__ post_base,
                                               const float* __restrict__ res_base,
                                               const float* __restrict__ a_pre,
                                               const float* __restrict__ a_post,
                                               const float* __restrict__ a_res) {
    const int b    = blockIdx.x >> 4;
    const int g    = blockIdx.x & 15;
    const int t    = threadIdx.x;
    const int lane = t & 31;
    const int warp = t >> 5;                 // 0..7
    const int col  = g * 256 + t;

    // finish mean over S for this column
    float x = 0.0f;
#pragma unroll
    for (int ch = 0; ch < SCHUNKS; ch++) x += g_partial[b][ch][col];
    x *= (1.0f / (float)SS);

    float acc24[NCOLS];
    const float* ph = phi + (size_t)col * NCOLS;
#pragma unroll
    for (int j = 0; j < NCOLS; j++) acc24[j] = x * ph[j];
    float ss = x * x;

#pragma unroll
    for (int o = 16; o > 0; o >>= 1) {
        ss += __shfl_down_sync(0xffffffffu, ss, o);
#pragma unroll
        for (int j = 0; j < NCOLS; j++)
            acc24[j] += __shfl_down_sync(0xffffffffu, acc24[j], o);
    }

    __shared__ float sred[8][NCOLS];
    __shared__ float sss[8];
    if (lane == 0) {
#pragma unroll
        for (int j = 0; j < NCOLS; j++) sred[warp][j] = acc24[j];
        sss[warp] = ss;
    }
    __syncthreads();

    if (t < NCOLS) {
        float v = 0.0f;
#pragma unroll
        for (int w = 0; w < 8; w++) v += sred[w][t];
        g_dpart[b][g][t] = v;
    } else if (t == NCOLS) {
        float v = 0.0f;
#pragma unroll
        for (int w = 0; w < 8; w++) v += sss[w];
        g_ssp[b][g] = v;
    }
    if (t <= NCOLS) __threadfence();
    __syncthreads();

    __shared__ int is_last;
    if (t == 0) {
        const unsigned old = atomicAdd(&g_gcnt, 1u);
        is_last = (old == (unsigned)(BB * GA - 1));
        if (is_last) atomicExch(&g_gcnt, 0u);    // self-reset for graph replay
        if (is_last) __threadfence();             // acquire all blocks' partials
    }
    __syncthreads();
    if (!is_last) return;

    // ---- finalize (last block; 4 warps = 4 batches) ----
    if (t < 128) {
        const int bb = t >> 5;
        const int ln = t & 31;

        __shared__ float sdelta[BB][NCOLS];

        float invrms = 0.0f;
        if (ln == 0) {
            float ssum = 0.0f;
#pragma unroll
            for (int k = 0; k < GA; k++) ssum += g_ssp[bb][k];
            invrms = 1.0f / sqrtf(ssum * (1.0f / (float)ND) + 1e-6f);
        }
        invrms = __shfl_sync(0xffffffffu, invrms, 0);

        if (ln < NCOLS) {
            float v = 0.0f;
#pragma unroll
            for (int k = 0; k < GA; k++) v += g_dpart[bb][k][ln];
            sdelta[bb][ln] = v * invrms;
        }
        __syncwarp();

        if (ln == 0) {
            const float ap  = *a_pre;
            const float apo = *a_post;
            const float ar  = *a_res;

            float pre[4];
            float psum = 0.0f;
#pragma unroll
            for (int k = 0; k < 4; k++) {
                pre[k] = 1.0f / (1.0f + expf(-(pre_base[k] + ap * sdelta[bb][k])));
                psum += pre[k];
            }
            const float pinv = 1.0f / (psum + 1e-8f);
#pragma unroll
            for (int k = 0; k < 4; k++) g_gates[bb][k] = pre[k] * pinv;

#pragma unroll
            for (int k = 0; k < 4; k++)
                g_gates[bb][4 + k] =
                    1.0f / (1.0f + expf(-(post_base[k] + apo * sdelta[bb][4 + k])));

            float P[16];
#pragma unroll
            for (int q = 0; q < 16; q++)
                P[q] = expf(res_base[q] + ar * sdelta[bb][8 + q]);
            for (int it = 0; it < 20; it++) {
#pragma unroll
                for (int i = 0; i < 4; i++) {
                    const float rs = P[i*4+0] + P[i*4+1] + P[i*4+2] + P[i*4+3];
                    const float inv = 1.0f / (rs + 1e-6f);
                    P[i*4+0] *= inv; P[i*4+1] *= inv; P[i*4+2] *= inv; P[i*4+3] *= inv;
                }
#pragma unroll
                for (int j = 0; j < 4; j++) {
                    const float cs = P[0*4+j] + P[1*4+j] + P[2*4+j] + P[3*4+j];
                    const float inv = 1.0f / (cs + 1e-6f);
                    P[0*4+j] *= inv; P[1*4+j] *= inv; P[2*4+j] *= inv; P[3*4+j] *= inv;
                }
            }
#pragma unroll
            for (int q = 0; q < 16; q++) g_gates[bb][8 + q] = P[q];
        }
    }
}

// ---------------------------------------------------------------------------
// Kernel 3: streaming mix, single launch; hot halves at low blockIdx (launch
// order), cold halves follow. One block per TWO rows. Loads .cs, stores .cs.
// ---------------------------------------------------------------------------
__global__ void __launch_bounds__(256) k_mix(const float* __restrict__ H,
                                             const float* __restrict__ bo,
                                             float* __restrict__ out) {
    const int idx   = blockIdx.x;            // 0..8191
    const int half  = idx >> 12;             // 0 = hot halves, 1 = cold
    const int rest  = idx & 4095;
    const int pair  = rest & 31;
    const int chunk = (rest >> 5) & 31;
    const int b     = rest >> 10;
    const int bs0   = b * SS + chunk * SPERCHUNK + half * 64 + pair * 2;
    const int bs1   = bs0 + 1;
    const int d4    = threadIdx.x;

    __shared__ float g[24];
    if (threadIdx.x < 24) g[threadIdx.x] = g_gates[b][threadIdx.x];

    const float4* hA = (const float4*)(H + (size_t)bs0 * ND);
    const float4* hB = (const float4*)(H + (size_t)bs1 * ND);

    const float4 a0 = __ldcs(hA + 0 * D4 + d4);
    const float4 a1 = __ldcs(hA + 1 * D4 + d4);
    const float4 a2 = __ldcs(hA + 2 * D4 + d4);
    const float4 a3 = __ldcs(hA + 3 * D4 + d4);
    const float4 av = __ldcs((const float4*)(bo + (size_t)bs0 * DD) + d4);
    const float4 b0 = __ldcs(hB + 0 * D4 + d4);
    const float4 b1 = __ldcs(hB + 1 * D4 + d4);
    const float4 b2 = __ldcs(hB + 2 * D4 + d4);
    const float4 b3 = __ldcs(hB + 3 * D4 + d4);
    const float4 bv = __ldcs((const float4*)(bo + (size_t)bs1 * DD) + d4);

    __syncthreads();

    float4* oA = (float4*)(out + (size_t)bs0 * 5 * DD);
    float4* oB = (float4*)(out + (size_t)bs1 * 5 * DD);

    {
        float4 o;
        o.x = g[0]*a0.x + g[1]*a1.x + g[2]*a2.x + g[3]*a3.x;
        o.y = g[0]*a0.y + g[1]*a1.y + g[2]*a2.y + g[3]*a3.y;
        o.z = g[0]*a0.z + g[1]*a1.z + g[2]*a2.z + g[3]*a3.z;
        o.w = g[0]*a0.w + g[1]*a1.w + g[2]*a2.w + g[3]*a3.w;
        __stcs(oA + d4, o);
        o.x = g[0]*b0.x + g[1]*b1.x + g[2]*b2.x + g[3]*b3.x;
        o.y = g[0]*b0.y + g[1]*b1.y + g[2]*b2.y + g[3]*b3.y;
        o.z = g[0]*b0.z + g[1]*b1.z + g[2]*b2.z + g[3]*b3.z;
        o.w = g[0]*b0.w + g[1]*b1.w + g[2]*b2.w + g[3]*b3.w;
        __stcs(oB + d4, o);
    }

#pragma unroll
    for (int i = 0; i < 4; i++) {
        const float r0 = g[8 + i * 4 + 0];
        const float r1 = g[8 + i * 4 + 1];
        const float r2 = g[8 + i * 4 + 2];
        const float r3 = g[8 + i * 4 + 3];
        const float p  = g[4 + i];
        float4 o;
        o.x = r0*a0.x + r1*a1.x + r2*a2.x + r3*a3.x + p*av.x;
        o.y = r0*a0.y + r1*a1.y + r2*a2.y + r3*a3.y + p*av.y;
        o.z = r0*a0.z + r1*a1.z + r2*a2.z + r3*a3.z + p*av.z;
        o.w = r0*a0.w + r1*a1.w + r2*a2.w + r3*a3.w + p*av.w;
        __stcs(oA + (1 + i) * D4 + d4, o);
        o.x = r0*b0.x + r1*b1.x + r2*b2.x + r3*b3.x + p*bv.x;
        o.y = r0*b0.y + r1*b1.y + r2*b2.y + r3*b3.y + p*bv.y;
        o.z = r0*b0.z + r1*b1.z + r2*b2.z + r3*b3.z + p*bv.z;
        o.w = r0*b0.w + r1*b1.w + r2*b2.w + r3*b3.w + p*bv.w;
        __stcs(oB + (1 + i) * D4 + d4, o);
    }
}

// ---------------------------------------------------------------------------
extern "C" void kernel_launch(void* const* d_in, const int* in_sizes, int n_in,
                              void* d_out, int out_size) {
    const float* H         = (const float*)d_in[0];
    const float* branch_o  = (const float*)d_in[1];
    const float* phi       = (const float*)d_in[2];
    const float* pre_base  = (const float*)d_in[3];
    const float* post_base = (const float*)d_in[4];
    const float* res_base  = (const float*)d_in[5];
    const float* a_pre     = (const float*)d_in[6];
    const float* a_post    = (const float*)d_in[7];
    const float* a_res     = (const float*)d_in[8];
    float* out = (float*)d_out;

    dim3 g1(ND4 / 256, SCHUNKS, BB);
    k_reduce<<<g1, 256>>>((const float4*)H);
    k_gates<<<BB * GA, 256>>>(phi, pre_base, post_base, res_base,
                              a_pre, a_post, a_res);
    const int mix_grid = (BB * SS) / 2;       // 8192 blocks, 2 rows each
    k_mix<<<mix_grid, 256>>>(H, branch_o, out);
}